// round 13
// baseline (speedup 1.0000x reference)
#include <cuda_runtime.h>
#include <math.h>

#define S_ 256
#define B_ 512
#define H_ 256
#define H3 768
#define VOCAB_ 32000
#define SSIZE 64
#define ELEM 64
#define NBLK 128
#define APAD 260   // A row stride (floats), 1040B, 16B multiple
#define BPAD 200   // B row stride (floats), 800B, 16B multiple

// ---------------- device scratch ----------------
__device__ float g_EMB_GI[VOCAB_ * H3];
__device__ float g_WihT[H_ * H3];
__device__ float g_WhhT[H_ * H3];
__device__ float g_WstkT[H_ * 128];
__device__ float g_Wa1T[H_ * H_];
__device__ float g_h[2][B_ * H_];
__device__ float g_spart[2][S_ * B_];
__device__ unsigned int g_bar;

__device__ __forceinline__ float sigmoidf_(float x) { return 1.f / (1.f + expf(-x)); }

// ---------------- cp.async helpers ----------------
__device__ __forceinline__ void cp16(float* dst_smem, const float* src) {
    unsigned d = (unsigned)__cvta_generic_to_shared(dst_smem);
    asm volatile("cp.async.cg.shared.global [%0], [%1], 16;" :: "r"(d), "l"(src));
}
__device__ __forceinline__ void cp_commit() { asm volatile("cp.async.commit_group;"); }
template <int N>
__device__ __forceinline__ void cp_wait() { asm volatile("cp.async.wait_group %0;" :: "n"(N)); }

// ---------------- prep (persist = my launch idx 3 = ncu slot 5) ----------------
__global__ void prep1(const float* __restrict__ W_ih, const float* __restrict__ W_hh) {
    int idx = blockIdx.x * 256 + threadIdx.x;
    if (idx < H3 * H_) {
        int r = idx % H3, c = idx / H3;
        g_WihT[idx] = W_ih[r * H_ + c];
        g_WhhT[idx] = W_hh[r * H_ + c];
    }
}
__global__ void prep2(const float* __restrict__ W_stk, const float* __restrict__ Wa1) {
    int idx = blockIdx.x * 256 + threadIdx.x;
    if (idx < 128 * H_) { int r = idx % 128, c = idx / 128; g_WstkT[idx] = W_stk[r * H_ + c]; }
    if (idx < H_ * H_) { int r = idx % H_, c = idx / H_; g_Wa1T[idx] = Wa1[r * H_ + c]; }
    if (idx < B_ * H_) g_h[0][idx] = 0.f;
    if (idx == 0) g_bar = 0u;
}

// ---------------- 128x128x16 SGEMM (plain FFMA) ----------------
template <bool SCORE>
__global__ void __launch_bounds__(256) sgemm128_k(
    const float* __restrict__ A, const float* __restrict__ Bm,
    const float* __restrict__ bias, float* __restrict__ C,
    const float* __restrict__ Wa2,
    int M, int N, int K)
{
    __shared__ __align__(16) float As[16][128];
    __shared__ __align__(16) float Bs[16][128];
    int tid = threadIdx.x;
    int m0 = blockIdx.y * 128, n0 = blockIdx.x * 128;
    int tx = tid & 15, ty = tid >> 4;
    float acc[2][2][4][4] = {};

    for (int k0 = 0; k0 < K; k0 += 16) {
#pragma unroll
        for (int i = 0; i < 2; i++) {
            int f = tid * 2 + i;
            int arow = f >> 2, aq = (f & 3) * 4;
            float4 v = *(const float4*)&A[(size_t)(m0 + arow) * K + k0 + aq];
            As[aq + 0][arow] = v.x; As[aq + 1][arow] = v.y;
            As[aq + 2][arow] = v.z; As[aq + 3][arow] = v.w;
            int brow = f >> 5, bc = (f & 31) * 4;
            *(float4*)&Bs[brow][bc] = *(const float4*)&Bm[(size_t)(k0 + brow) * N + n0 + bc];
        }
        __syncthreads();
#pragma unroll
        for (int kk = 0; kk < 16; kk++) {
            float a[2][4], b[2][4];
            *(float4*)a[0] = *(float4*)&As[kk][ty * 4];
            *(float4*)a[1] = *(float4*)&As[kk][ty * 4 + 64];
            *(float4*)b[0] = *(float4*)&Bs[kk][tx * 4];
            *(float4*)b[1] = *(float4*)&Bs[kk][tx * 4 + 64];
#pragma unroll
            for (int ic = 0; ic < 2; ic++)
#pragma unroll
                for (int jc = 0; jc < 2; jc++)
#pragma unroll
                    for (int i = 0; i < 4; i++)
#pragma unroll
                        for (int j = 0; j < 4; j++)
                            acc[ic][jc][i][j] = fmaf(a[ic][i], b[jc][j], acc[ic][jc][i][j]);
        }
        __syncthreads();
    }

    if (!SCORE) {
#pragma unroll
        for (int ic = 0; ic < 2; ic++)
#pragma unroll
            for (int i = 0; i < 4; i++) {
                int m = m0 + ic * 64 + ty * 4 + i;
#pragma unroll
                for (int jc = 0; jc < 2; jc++) {
                    int n = n0 + jc * 64 + tx * 4;
                    float4 o;
                    o.x = acc[ic][jc][i][0] + bias[n + 0];
                    o.y = acc[ic][jc][i][1] + bias[n + 1];
                    o.z = acc[ic][jc][i][2] + bias[n + 2];
                    o.w = acc[ic][jc][i][3] + bias[n + 3];
                    *(float4*)&C[(size_t)m * N + n] = o;
                }
            }
    } else {
        float4 bb[2], ww[2];
#pragma unroll
        for (int jc = 0; jc < 2; jc++) {
            int n = n0 + jc * 64 + tx * 4;
            bb[jc] = *(const float4*)&bias[n];
            ww[jc] = *(const float4*)&Wa2[n];
        }
#pragma unroll
        for (int ic = 0; ic < 2; ic++)
#pragma unroll
            for (int i = 0; i < 4; i++) {
                float p = 0.f;
#pragma unroll
                for (int jc = 0; jc < 2; jc++) {
                    p += tanhf(acc[ic][jc][i][0] + bb[jc].x) * ww[jc].x;
                    p += tanhf(acc[ic][jc][i][1] + bb[jc].y) * ww[jc].y;
                    p += tanhf(acc[ic][jc][i][2] + bb[jc].z) * ww[jc].z;
                    p += tanhf(acc[ic][jc][i][3] + bb[jc].w) * ww[jc].w;
                }
#pragma unroll
                for (int off = 8; off > 0; off >>= 1)
                    p += __shfl_xor_sync(0xffffffffu, p, off);
                if (tx == 0) {
                    int m = m0 + ic * 64 + ty * 4 + i;
                    g_spart[blockIdx.x][m] = p;
                }
            }
    }
}

// ---------------- persistent recurrence: 128 uniform blocks, 1/SM ----------------
// GRU warp = 4 rows x 32 j-cols (thread = 1 row x 4 cols x 3 gates): B-addresses
// duplicated 4x in-warp -> LDS broadcast halves B smem traffic vs R12.
// AUX: direct-from-L2 __ldcg GEMM, no staging/syncs. 8 SMEM stacks per block.
#define OFF_STK  0                     // 8 * 4096 = 32768
#define OFF_A    32768                 // [16][APAD] = 4160
#define OFF_AA   36928                 // [4][APAD]  = 1040
#define OFF_B    37968                 // 2 * 16*BPAD = 6400
#define OFF_PV   44368                 // 2 * 512    = 1024
#define OFF_P    45392                 // 2 * 24     = 48
#define OFF_LG   45440                 // 24
#define SMEM_DYN ((45472 + 8) * 4)

__global__ void __launch_bounds__(256, 1) persist_k(
    const int* __restrict__ tokens,
    const float* __restrict__ b_ih,
    const float* __restrict__ b_hh,
    const float* __restrict__ W_act,
    const float* __restrict__ b_act,
    const float* __restrict__ b_stk,
    const float* __restrict__ empty_elem,
    float* __restrict__ outputs,
    float* __restrict__ stacks_out)
{
    extern __shared__ __align__(16) float smem[];
    float* stk   = smem + OFF_STK;
    float* A     = smem + OFF_A;
    float* Aa    = smem + OFF_AA;
    float* B0    = smem + OFF_B;
    float* pvbuf = smem + OFF_PV;
    float* pbuf  = smem + OFF_P;
    float* lg    = smem + OFF_LG;

    int tid = threadIdx.x, blk = blockIdx.x;
    float emp = empty_elem[tid & 63];

    for (int i = tid; i < 8 * 4096; i += 256) stk[i] = empty_elem[i & 63];

    // GRU mapping: block tile 16 batches x 64 j (x3 gates)
    int b0 = (blk >> 2) * 16, j0 = (blk & 3) * 64;
    int w = tid >> 5, l = tid & 31;
    int grow = (w & 3) * 4 + (l >> 3);        // 0..15
    int jo   = (w >> 2) * 32 + (l & 7) * 4;   // 0..60, 16B aligned
    int r0 = b0 + grow;
    // AUX mapping
    int ab0 = blk * 4;
    int acol = tid & 127;
    int ab   = (tid >> 7) * 2;
    int wwid = w, lane = l;

    for (int s = 0; s < S_; s++) {
        const float* hin = g_h[s & 1];
        float* hout = g_h[(s + 1) & 1];

        // ---- stage A (16 GRU rows) + Aa (4 AUX rows) ----
        {
            int m = tid >> 4, kq = (tid & 15) * 16;
            const float* src = hin + (b0 + m) * H_ + kq;
            float4 v0 = __ldcg((const float4*)(src + 0));
            float4 v1 = __ldcg((const float4*)(src + 4));
            float4 v2 = __ldcg((const float4*)(src + 8));
            float4 v3 = __ldcg((const float4*)(src + 12));
            float* d = A + m * APAD + kq;
            *(float4*)(d + 0) = v0; *(float4*)(d + 4)  = v1;
            *(float4*)(d + 8) = v2; *(float4*)(d + 12) = v3;
        }
        {
            int m = tid >> 6, kq = (tid & 63) * 4;
            float4 v = __ldcg((const float4*)(hin + (ab0 + m) * H_ + kq));
            *(float4*)(Aa + m * APAD + kq) = v;
        }

        // ---- GRU epilogue operand prefetch (hidden under GEMM) ----
        int jj = j0 + jo;
        int tok = __ldg(&tokens[s * B_ + r0]);
        const float* gi = (tok == 0) ? b_ih : (g_EMB_GI + (size_t)tok * H3);
        float4 gr = *(const float4*)(gi + jj);
        float4 gz = *(const float4*)(gi + H_ + jj);
        float4 gn = *(const float4*)(gi + 2 * H_ + jj);
        float4 hp = __ldcg((const float4*)(hin + r0 * H_ + jj));

        // ---- GRU B chunk 0 prefetch ----
#pragma unroll
        for (int i = 0; i < 3; i++) {
            int idx = tid + i * 256;
            int kk = idx / 48, r = idx % 48, g = r >> 4, lq = r & 15;
            cp16(B0 + kk * BPAD + g * 64 + lq * 4,
                 g_WhhT + (size_t)kk * H3 + g * H_ + j0 + lq * 4);
        }
        cp_commit();

        float4 accr = {0,0,0,0}, accz = {0,0,0,0}, accn = {0,0,0,0};
        __syncthreads();   // A, Aa visible

        for (int c = 0; c < 16; c++) {
            float* Bc = B0 + (c & 1) * (16 * BPAD);
            if (c + 1 < 16) {
                float* Bn = B0 + ((c + 1) & 1) * (16 * BPAD);
                int kb = (c + 1) * 16;
#pragma unroll
                for (int i = 0; i < 3; i++) {
                    int idx = tid + i * 256;
                    int kk = idx / 48, r = idx % 48, g = r >> 4, lq = r & 15;
                    cp16(Bn + kk * BPAD + g * 64 + lq * 4,
                         g_WhhT + (size_t)(kb + kk) * H3 + g * H_ + j0 + lq * 4);
                }
                cp_commit();
                cp_wait<1>();
            } else {
                cp_wait<0>();
            }
            __syncthreads();
            // hoist this thread's A-row chunk (broadcast across 8 lanes)
            float a[16];
            {
                const float4* Ar = (const float4*)(A + grow * APAD + c * 16);
                *(float4*)&a[0]  = Ar[0];
                *(float4*)&a[4]  = Ar[1];
                *(float4*)&a[8]  = Ar[2];
                *(float4*)&a[12] = Ar[3];
            }
#pragma unroll
            for (int kk = 0; kk < 16; kk++) {
                float av = a[kk];
                float4 br = *(float4*)(Bc + kk * BPAD + jo);
                float4 bz = *(float4*)(Bc + kk * BPAD + 64 + jo);
                float4 bn = *(float4*)(Bc + kk * BPAD + 128 + jo);
                accr.x = fmaf(av, br.x, accr.x); accr.y = fmaf(av, br.y, accr.y);
                accr.z = fmaf(av, br.z, accr.z); accr.w = fmaf(av, br.w, accr.w);
                accz.x = fmaf(av, bz.x, accz.x); accz.y = fmaf(av, bz.y, accz.y);
                accz.z = fmaf(av, bz.z, accz.z); accz.w = fmaf(av, bz.w, accz.w);
                accn.x = fmaf(av, bn.x, accn.x); accn.y = fmaf(av, bn.y, accn.y);
                accn.z = fmaf(av, bn.z, accn.z); accn.w = fmaf(av, bn.w, accn.w);
            }
            __syncthreads();
        }

        // ---- GRU epilogue (1 row x 4 cols) ----
        {
            float4 bhr = *(const float4*)(b_hh + jj);
            float4 bhz = *(const float4*)(b_hh + H_ + jj);
            float4 bhn = *(const float4*)(b_hh + 2 * H_ + jj);
            float4 o;
            { float rr = sigmoidf_(gr.x + accr.x + bhr.x);
              float zz = sigmoidf_(gz.x + accz.x + bhz.x);
              float nn = tanhf(gn.x + rr * (accn.x + bhn.x));
              o.x = (1.f - zz) * nn + zz * hp.x; }
            { float rr = sigmoidf_(gr.y + accr.y + bhr.y);
              float zz = sigmoidf_(gz.y + accz.y + bhz.y);
              float nn = tanhf(gn.y + rr * (accn.y + bhn.y));
              o.y = (1.f - zz) * nn + zz * hp.y; }
            { float rr = sigmoidf_(gr.z + accr.z + bhr.z);
              float zz = sigmoidf_(gz.z + accz.z + bhz.z);
              float nn = tanhf(gn.z + rr * (accn.z + bhn.z));
              o.z = (1.f - zz) * nn + zz * hp.z; }
            { float rr = sigmoidf_(gr.w + accr.w + bhr.w);
              float zz = sigmoidf_(gz.w + accz.w + bhz.w);
              float nn = tanhf(gn.w + rr * (accn.w + bhn.w));
              o.w = (1.f - zz) * nn + zz * hp.w; }
            *(float4*)(hout + r0 * H_ + jj) = o;
            *(float4*)(outputs + ((size_t)s * B_ + r0) * H_ + jj) = o;
        }

        // ---- AUX GEMM direct from L2: PV[ab..ab+1][acol] ----
        {
            const float* a0r = Aa + ab * APAD;
            const float* a1r = Aa + (ab + 1) * APAD;
            float s0 = 0.f, s1 = 0.f;
#pragma unroll 8
            for (int k = 0; k < H_; k++) {
                float wv = __ldcg(&g_WstkT[k * 128 + acol]);
                s0 = fmaf(a0r[k], wv, s0);
                s1 = fmaf(a1r[k], wv, s1);
            }
            float bs = __ldg(&b_stk[acol]);
            float* pv = pvbuf + (s & 1) * 512;
            pv[ab * 128 + acol]       = tanhf(s0 + bs);
            pv[(ab + 1) * 128 + acol] = tanhf(s1 + bs);
        }

        // ---- ACT logits: 24 dots, 3 per warp, shfl-reduced ----
#pragma unroll
        for (int q = 0; q < 3; q++) {
            int d = wwid * 3 + q;
            int bl = d / 6, o = d % 6;
            const float* ar = Aa + bl * APAD;
            const float* wr = W_act + o * H_;
            float sum = 0.f;
#pragma unroll
            for (int k = lane; k < H_; k += 32)
                sum = fmaf(ar[k], __ldg(&wr[k]), sum);
#pragma unroll
            for (int off = 16; off > 0; off >>= 1)
                sum += __shfl_xor_sync(0xffffffffu, sum, off);
            if (lane == 0) lg[d] = sum + __ldg(&b_act[o]);
        }
        __syncthreads();
        if (tid < 8) {
            float l0 = lg[tid * 3 + 0], l1 = lg[tid * 3 + 1], l2 = lg[tid * 3 + 2];
            float mx = fmaxf(l0, fmaxf(l1, l2));
            float e0 = expf(l0 - mx), e1 = expf(l1 - mx), e2 = expf(l2 - mx);
            float inv = 1.f / (e0 + e1 + e2);
            float* P = pbuf + (s & 1) * 24 + tid * 3;
            P[0] = e0 * inv; P[1] = e1 * inv; P[2] = e2 * inv;
        }

        // ---- arrive ----
        __threadfence();
        __syncthreads();
        if (tid == 0) atomicAdd(&g_bar, 1u);

        // ---- stack update for step s-1 (block-local, hidden in wait window) ----
        if (s > 0) {
            int ph = (s - 1) & 1;
#pragma unroll
            for (int half = 0; half < 2; half++) {
                int col = tid + half * 256;
                int stl = col >> 6, ee = col & 63;
                float pp = pbuf[ph * 24 + stl * 3 + 0];
                float po = pbuf[ph * 24 + stl * 3 + 1];
                float pn = pbuf[ph * 24 + stl * 3 + 2];
                float pvv = pvbuf[ph * 512 + (stl >> 1) * 128 + (stl & 1) * 64 + ee];
                float* Sm = stk + stl * 4096;
                float prev = 0.f, cur = Sm[ee];
                float first = pp * pvv;
#pragma unroll 16
                for (int row = 0; row < SSIZE; row++) {
                    float nxt = (row < SSIZE - 1) ? Sm[(row + 1) * 64 + ee] : 0.f;
                    float v;
                    if (row == 0)              v = first;
                    else if (row == SSIZE - 1) v = emp;
                    else v = fmaf(pp, prev, fmaf(po, nxt, pn * cur));
                    Sm[row * 64 + ee] = v;
                    prev = cur; cur = nxt;
                }
            }
        }

        // ---- spin ----
        if (tid == 0) {
            unsigned int target = (unsigned int)NBLK * (unsigned int)(s + 1);
            while (*((volatile unsigned int*)&g_bar) < target) { }
        }
        __syncthreads();
    }

    // ---- final stack update (step S-1) -> global ----
    {
        int ph = (S_ - 1) & 1;
#pragma unroll
        for (int half = 0; half < 2; half++) {
            int col = tid + half * 256;
            int stl = col >> 6, ee = col & 63;
            float pp = pbuf[ph * 24 + stl * 3 + 0];
            float po = pbuf[ph * 24 + stl * 3 + 1];
            float pn = pbuf[ph * 24 + stl * 3 + 2];
            float pvv = pvbuf[ph * 512 + (stl >> 1) * 128 + (stl & 1) * 64 + ee];
            float* Sm = stk + stl * 4096;
            float* dst = stacks_out + (size_t)(blk * 8 + stl) * 4096;
            float prev = 0.f, cur = Sm[ee];
            float first = pp * pvv;
#pragma unroll 16
            for (int row = 0; row < SSIZE; row++) {
                float nxt = (row < SSIZE - 1) ? Sm[(row + 1) * 64 + ee] : 0.f;
                float v;
                if (row == 0)              v = first;
                else if (row == SSIZE - 1) v = emp;
                else v = fmaf(pp, prev, fmaf(po, nxt, pn * cur));
                dst[row * 64 + ee] = v;
                prev = cur; cur = nxt;
            }
        }
    }
}

// ---------------- softmax over S + weighted sum -> final_hidden ----------------
__global__ void __launch_bounds__(256) attn_final_k(const float* __restrict__ outputs,
                                                    const int* __restrict__ tokens,
                                                    const float* __restrict__ ba2,
                                                    float* __restrict__ fh) {
    int b = blockIdx.x;
    int tid = threadIdx.x;
    int lane = tid & 31, wid = tid >> 5;
    __shared__ float a_sm[S_];
    __shared__ float rmax[8];
    __shared__ float rsum[8];

    float v = g_spart[0][tid * B_ + b] + g_spart[1][tid * B_ + b] + ba2[0];
    if (tokens[tid * B_ + b] == 0) v = -1e30f;

    float m = v;
#pragma unroll
    for (int off = 16; off > 0; off >>= 1) m = fmaxf(m, __shfl_xor_sync(0xffffffffu, m, off));
    if (lane == 0) rmax[wid] = m;
    __syncthreads();
    float mx = rmax[0];
#pragma unroll
    for (int i = 1; i < 8; i++) mx = fmaxf(mx, rmax[i]);
    float e = expf(v - mx);
    float sum = e;
#pragma unroll
    for (int off = 16; off > 0; off >>= 1) sum += __shfl_xor_sync(0xffffffffu, sum, off);
    if (lane == 0) rsum[wid] = sum;
    __syncthreads();
    float tot = rsum[0];
#pragma unroll
    for (int i = 1; i < 8; i++) tot += rsum[i];
    a_sm[tid] = e / tot;
    __syncthreads();

    float acc = 0.f;
    for (int s2 = 0; s2 < S_; s2++)
        acc += a_sm[s2] * outputs[((size_t)s2 * B_ + b) * H_ + tid];
    fh[b * H_ + tid] = acc;
}

// ---------------- launch ----------------
extern "C" void kernel_launch(void* const* d_in, const int* in_sizes, int n_in,
                              void* d_out, int out_size) {
    const int*   tokens     = (const int*)d_in[0];
    const float* emb        = (const float*)d_in[1];
    const float* W_ih       = (const float*)d_in[2];
    const float* W_hh       = (const float*)d_in[3];
    const float* b_ih       = (const float*)d_in[4];
    const float* b_hh       = (const float*)d_in[5];
    const float* W_act      = (const float*)d_in[6];
    const float* b_act      = (const float*)d_in[7];
    const float* W_stk      = (const float*)d_in[8];
    const float* b_stk      = (const float*)d_in[9];
    const float* empty_elem = (const float*)d_in[10];
    // d_in[11]=W_up, d_in[12]=W_down : shift matrices, hardcoded
    const float* Wa1        = (const float*)d_in[13];
    const float* ba1        = (const float*)d_in[14];
    const float* Wa2        = (const float*)d_in[15];
    const float* ba2        = (const float*)d_in[16];

    float* out     = (float*)d_out;
    float* outputs = out;
    float* fh      = out + (size_t)S_ * B_ * H_;
    float* stacks  = fh + (size_t)B_ * H_;

    float *pWihT, *pWa1T, *pEMB;
    cudaGetSymbolAddress((void**)&pWihT, g_WihT);
    cudaGetSymbolAddress((void**)&pWa1T, g_Wa1T);
    cudaGetSymbolAddress((void**)&pEMB,  g_EMB_GI);

    static int smem_set = 0;
    if (!smem_set) {
        cudaFuncSetAttribute(persist_k, cudaFuncAttributeMaxDynamicSharedMemorySize, SMEM_DYN);
        smem_set = 1;
    }

    // idx 0-1: prep
    prep1<<<(H3 * H_ + 255) / 256, 256>>>(W_ih, W_hh);
    prep2<<<(B_ * H_ + 255) / 256, 256>>>(W_stk, Wa1);

    // idx 2: EMB_GI = emb @ W_ih^T + b_ih
    {
        dim3 grid(H3 / 128, VOCAB_ / 128);
        sgemm128_k<false><<<grid, 256>>>(emb, pWihT, b_ih, pEMB, nullptr, VOCAB_, H3, H_);
    }

    // idx 3: the whole recurrence (ncu capture slot 5)
    persist_k<<<NBLK, 256, SMEM_DYN>>>(tokens, b_ih, b_hh, W_act, b_act, b_stk,
                                       empty_elem, outputs, stacks);

    // idx 4: attention partials
    {
        dim3 grid(H_ / 128, (S_ * B_) / 128);
        sgemm128_k<true><<<grid, 256>>>(outputs, pWa1T, ba1, nullptr, Wa2, S_ * B_, H_, H_);
    }
    // idx 5: softmax + weighted sum
    attn_final_k<<<B_, 256>>>(outputs, tokens, ba2, fh);
}

// round 14
// speedup vs baseline: 1.5093x; 1.5093x over previous
#include <cuda_runtime.h>
#include <math.h>

#define S_ 256
#define B_ 512
#define H_ 256
#define H3 768
#define VOCAB_ 32000
#define SSIZE 64
#define ELEM 64
#define NBLK 128
#define APAD 260   // Aa row stride (floats)
#define BPAD 200   // B row stride (floats), 800B, 16B multiple
#define ATS 20     // A_T row stride (floats), 80B, 16B multiple

// ---------------- device scratch ----------------
__device__ float g_EMB_GI[VOCAB_ * H3];
__device__ float g_WihT[H_ * H3];
__device__ float g_WhhT[H_ * H3];
__device__ float g_WstkT[H_ * 128];
__device__ float g_Wa1T[H_ * H_];
__device__ float g_h[2][B_ * H_];
__device__ float g_spart[2][S_ * B_];
__device__ unsigned int g_bar;

__device__ __forceinline__ float sigmoidf_(float x) { return 1.f / (1.f + expf(-x)); }

// ---------------- cp.async helpers ----------------
__device__ __forceinline__ void cp16(float* dst_smem, const float* src) {
    unsigned d = (unsigned)__cvta_generic_to_shared(dst_smem);
    asm volatile("cp.async.cg.shared.global [%0], [%1], 16;" :: "r"(d), "l"(src));
}
__device__ __forceinline__ void cp_commit() { asm volatile("cp.async.commit_group;"); }
template <int N>
__device__ __forceinline__ void cp_wait() { asm volatile("cp.async.wait_group %0;" :: "n"(N)); }

// ---------------- prep (persist = my launch idx 3 = ncu slot 5) ----------------
__global__ void prep1(const float* __restrict__ W_ih, const float* __restrict__ W_hh) {
    int idx = blockIdx.x * 256 + threadIdx.x;
    if (idx < H3 * H_) {
        int r = idx % H3, c = idx / H3;
        g_WihT[idx] = W_ih[r * H_ + c];
        g_WhhT[idx] = W_hh[r * H_ + c];
    }
}
__global__ void prep2(const float* __restrict__ W_stk, const float* __restrict__ Wa1) {
    int idx = blockIdx.x * 256 + threadIdx.x;
    if (idx < 128 * H_) { int r = idx % 128, c = idx / 128; g_WstkT[idx] = W_stk[r * H_ + c]; }
    if (idx < H_ * H_) { int r = idx % H_, c = idx / H_; g_Wa1T[idx] = Wa1[r * H_ + c]; }
    if (idx < B_ * H_) g_h[0][idx] = 0.f;
    if (idx == 0) g_bar = 0u;
}

// ---------------- 128x128x16 SGEMM (plain FFMA) ----------------
template <bool SCORE>
__global__ void __launch_bounds__(256) sgemm128_k(
    const float* __restrict__ A, const float* __restrict__ Bm,
    const float* __restrict__ bias, float* __restrict__ C,
    const float* __restrict__ Wa2,
    int M, int N, int K)
{
    __shared__ __align__(16) float As[16][128];
    __shared__ __align__(16) float Bs[16][128];
    int tid = threadIdx.x;
    int m0 = blockIdx.y * 128, n0 = blockIdx.x * 128;
    int tx = tid & 15, ty = tid >> 4;
    float acc[2][2][4][4] = {};

    for (int k0 = 0; k0 < K; k0 += 16) {
#pragma unroll
        for (int i = 0; i < 2; i++) {
            int f = tid * 2 + i;
            int arow = f >> 2, aq = (f & 3) * 4;
            float4 v = *(const float4*)&A[(size_t)(m0 + arow) * K + k0 + aq];
            As[aq + 0][arow] = v.x; As[aq + 1][arow] = v.y;
            As[aq + 2][arow] = v.z; As[aq + 3][arow] = v.w;
            int brow = f >> 5, bc = (f & 31) * 4;
            *(float4*)&Bs[brow][bc] = *(const float4*)&Bm[(size_t)(k0 + brow) * N + n0 + bc];
        }
        __syncthreads();
#pragma unroll
        for (int kk = 0; kk < 16; kk++) {
            float a[2][4], b[2][4];
            *(float4*)a[0] = *(float4*)&As[kk][ty * 4];
            *(float4*)a[1] = *(float4*)&As[kk][ty * 4 + 64];
            *(float4*)b[0] = *(float4*)&Bs[kk][tx * 4];
            *(float4*)b[1] = *(float4*)&Bs[kk][tx * 4 + 64];
#pragma unroll
            for (int ic = 0; ic < 2; ic++)
#pragma unroll
                for (int jc = 0; jc < 2; jc++)
#pragma unroll
                    for (int i = 0; i < 4; i++)
#pragma unroll
                        for (int j = 0; j < 4; j++)
                            acc[ic][jc][i][j] = fmaf(a[ic][i], b[jc][j], acc[ic][jc][i][j]);
        }
        __syncthreads();
    }

    if (!SCORE) {
#pragma unroll
        for (int ic = 0; ic < 2; ic++)
#pragma unroll
            for (int i = 0; i < 4; i++) {
                int m = m0 + ic * 64 + ty * 4 + i;
#pragma unroll
                for (int jc = 0; jc < 2; jc++) {
                    int n = n0 + jc * 64 + tx * 4;
                    float4 o;
                    o.x = acc[ic][jc][i][0] + bias[n + 0];
                    o.y = acc[ic][jc][i][1] + bias[n + 1];
                    o.z = acc[ic][jc][i][2] + bias[n + 2];
                    o.w = acc[ic][jc][i][3] + bias[n + 3];
                    *(float4*)&C[(size_t)m * N + n] = o;
                }
            }
    } else {
        float4 bb[2], ww[2];
#pragma unroll
        for (int jc = 0; jc < 2; jc++) {
            int n = n0 + jc * 64 + tx * 4;
            bb[jc] = *(const float4*)&bias[n];
            ww[jc] = *(const float4*)&Wa2[n];
        }
#pragma unroll
        for (int ic = 0; ic < 2; ic++)
#pragma unroll
            for (int i = 0; i < 4; i++) {
                float p = 0.f;
#pragma unroll
                for (int jc = 0; jc < 2; jc++) {
                    p += tanhf(acc[ic][jc][i][0] + bb[jc].x) * ww[jc].x;
                    p += tanhf(acc[ic][jc][i][1] + bb[jc].y) * ww[jc].y;
                    p += tanhf(acc[ic][jc][i][2] + bb[jc].z) * ww[jc].z;
                    p += tanhf(acc[ic][jc][i][3] + bb[jc].w) * ww[jc].w;
                }
#pragma unroll
                for (int off = 8; off > 0; off >>= 1)
                    p += __shfl_xor_sync(0xffffffffu, p, off);
                if (tx == 0) {
                    int m = m0 + ic * 64 + ty * 4 + i;
                    g_spart[blockIdx.x][m] = p;
                }
            }
    }
}

// ---------------- persistent recurrence: 128 uniform blocks, 1/SM ----------------
// GRU: thread = 4 rows x 1 j-col x 3 gates. B = 3x LDS.32 (1 phase each),
// A = k-major smem, 1x LDS.128 broadcast per kk. 4 phases/warp-kk vs 6 FFMA-pipe
// cycles -> FFMA-bound. AUX/ACT/stacks identical to R12 (best known).
#define OFF_STK  0                     // 32768
#define OFF_AT   32768                 // 256*ATS = 5120
#define OFF_AA   37888                 // [4][APAD] = 1040
#define OFF_B    38928                 // 2 * 16*BPAD = 6400
#define OFF_BA   45328                 // 2 * 2112 = 4224
#define OFF_PV   49552                 // 2 * 512 = 1024
#define OFF_P    50576                 // 48
#define OFF_LG   50624                 // 24
#define SMEM_DYN ((50656) * 4)

__global__ void __launch_bounds__(256, 1) persist_k(
    const int* __restrict__ tokens,
    const float* __restrict__ b_ih,
    const float* __restrict__ b_hh,
    const float* __restrict__ W_act,
    const float* __restrict__ b_act,
    const float* __restrict__ b_stk,
    const float* __restrict__ empty_elem,
    float* __restrict__ outputs,
    float* __restrict__ stacks_out)
{
    extern __shared__ __align__(16) float smem[];
    float* stk   = smem + OFF_STK;
    float* AT    = smem + OFF_AT;     // [k(256)][16 rows + pad4]
    float* Aa    = smem + OFF_AA;
    float* B0    = smem + OFF_B;
    float* BsA   = smem + OFF_BA;
    float* pvbuf = smem + OFF_PV;
    float* pbuf  = smem + OFF_P;
    float* lg    = smem + OFF_LG;

    int tid = threadIdx.x, blk = blockIdx.x;
    float emp = empty_elem[tid & 63];

    for (int i = tid; i < 8 * 4096; i += 256) stk[i] = empty_elem[i & 63];

    // GRU mapping: tile 16 batches x 64 j (x3 gates)
    int b0 = (blk >> 2) * 16, j0 = (blk & 3) * 64;
    int w = tid >> 5, l = tid & 31;
    int gr0 = (w & 3) * 4;                 // first of 4 rows
    int jo  = (w >> 2) * 32 + l;           // j col 0..63
    // AUX mapping (R12)
    int ab0 = blk * 4;
    int aty = tid >> 6, atx = tid & 63;
    int wwid = w, lane = l;

    for (int s = 0; s < S_; s++) {
        const float* hin = g_h[s & 1];
        float* hout = g_h[(s + 1) & 1];

        // ---- stage A_T (k-major, 16 rows) + Aa (4 AUX rows) ----
        {
            int m = tid >> 4, kq = (tid & 15) * 16;
            const float* src = hin + (b0 + m) * H_ + kq;
            float4 v0 = __ldcg((const float4*)(src + 0));
            float4 v1 = __ldcg((const float4*)(src + 4));
            float4 v2 = __ldcg((const float4*)(src + 8));
            float4 v3 = __ldcg((const float4*)(src + 12));
            float* d = AT + kq * ATS + m;
            d[0*ATS]=v0.x; d[1*ATS]=v0.y; d[2*ATS]=v0.z; d[3*ATS]=v0.w;
            d[4*ATS]=v1.x; d[5*ATS]=v1.y; d[6*ATS]=v1.z; d[7*ATS]=v1.w;
            d[8*ATS]=v2.x; d[9*ATS]=v2.y; d[10*ATS]=v2.z; d[11*ATS]=v2.w;
            d[12*ATS]=v3.x; d[13*ATS]=v3.y; d[14*ATS]=v3.z; d[15*ATS]=v3.w;
        }
        {
            int m = tid >> 6, kq = (tid & 63) * 4;
            float4 v = __ldcg((const float4*)(hin + (ab0 + m) * H_ + kq));
            *(float4*)(Aa + m * APAD + kq) = v;
        }

        // ---- GRU epilogue operand prefetch (hidden under GEMM) ----
        int jj = j0 + jo;
        float grv[4], gzv[4], gnv[4], hpv[4];
#pragma unroll
        for (int i = 0; i < 4; i++) {
            int row = b0 + gr0 + i;
            int tok = __ldg(&tokens[s * B_ + row]);
            const float* gi = (tok == 0) ? b_ih : (g_EMB_GI + (size_t)tok * H3);
            grv[i] = __ldg(gi + jj);
            gzv[i] = __ldg(gi + H_ + jj);
            gnv[i] = __ldg(gi + 2 * H_ + jj);
            hpv[i] = __ldcg(hin + row * H_ + jj);
        }

        // ---- GRU B chunk 0 prefetch ----
#pragma unroll
        for (int i = 0; i < 3; i++) {
            int idx = tid + i * 256;
            int kk = idx / 48, r = idx % 48, g = r >> 4, lq = r & 15;
            cp16(B0 + kk * BPAD + g * 64 + lq * 4,
                 g_WhhT + (size_t)kk * H3 + g * H_ + j0 + lq * 4);
        }
        cp_commit();

        float accr[4] = {}, accz[4] = {}, accn[4] = {};
        __syncthreads();   // AT, Aa visible

        for (int c = 0; c < 16; c++) {
            float* Bc = B0 + (c & 1) * (16 * BPAD);
            if (c + 1 < 16) {
                float* Bn = B0 + ((c + 1) & 1) * (16 * BPAD);
                int kb = (c + 1) * 16;
#pragma unroll
                for (int i = 0; i < 3; i++) {
                    int idx = tid + i * 256;
                    int kk = idx / 48, r = idx % 48, g = r >> 4, lq = r & 15;
                    cp16(Bn + kk * BPAD + g * 64 + lq * 4,
                         g_WhhT + (size_t)(kb + kk) * H3 + g * H_ + j0 + lq * 4);
                }
                cp_commit();
                cp_wait<1>();
            } else {
                cp_wait<0>();
            }
            __syncthreads();
            const float* ATc = AT + (c * 16) * ATS + gr0;
#pragma unroll
            for (int kk = 0; kk < 16; kk++) {
                float4 av = *(const float4*)(ATc + kk * ATS);   // broadcast, 1 phase
                float br = Bc[kk * BPAD + jo];
                float bz = Bc[kk * BPAD + 64 + jo];
                float bn = Bc[kk * BPAD + 128 + jo];
                accr[0] = fmaf(av.x, br, accr[0]); accr[1] = fmaf(av.y, br, accr[1]);
                accr[2] = fmaf(av.z, br, accr[2]); accr[3] = fmaf(av.w, br, accr[3]);
                accz[0] = fmaf(av.x, bz, accz[0]); accz[1] = fmaf(av.y, bz, accz[1]);
                accz[2] = fmaf(av.z, bz, accz[2]); accz[3] = fmaf(av.w, bz, accz[3]);
                accn[0] = fmaf(av.x, bn, accn[0]); accn[1] = fmaf(av.y, bn, accn[1]);
                accn[2] = fmaf(av.z, bn, accn[2]); accn[3] = fmaf(av.w, bn, accn[3]);
            }
            __syncthreads();
        }

        // ---- GRU epilogue (4 rows x 1 col) ----
        {
            float bhr = __ldg(b_hh + jj);
            float bhz = __ldg(b_hh + H_ + jj);
            float bhn = __ldg(b_hh + 2 * H_ + jj);
#pragma unroll
            for (int i = 0; i < 4; i++) {
                int row = b0 + gr0 + i;
                float rr = sigmoidf_(grv[i] + accr[i] + bhr);
                float zz = sigmoidf_(gzv[i] + accz[i] + bhz);
                float nn = tanhf(gnv[i] + rr * (accn[i] + bhn));
                float o = (1.f - zz) * nn + zz * hpv[i];
                hout[row * H_ + jj] = o;
                outputs[((size_t)s * B_ + row) * H_ + jj] = o;
            }
        }

        // ---- AUX GEMM (R12 verbatim): PV = tanh(h[ab0..+3] @ WstkT + b_stk) ----
#pragma unroll
        for (int i = 0; i < 2; i++) {
            int idx = tid + i * 256;
            int kk = idx >> 5, lq = idx & 31;
            cp16(BsA + kk * 132 + lq * 4, g_WstkT + (size_t)kk * 128 + lq * 4);
        }
        cp_commit();
        float acc0 = 0.f, acc1 = 0.f;
        for (int c = 0; c < 16; c++) {
            float* Bc = BsA + (c & 1) * 2112;
            if (c + 1 < 16) {
                float* Bn = BsA + ((c + 1) & 1) * 2112;
                int kb = (c + 1) * 16;
#pragma unroll
                for (int i = 0; i < 2; i++) {
                    int idx = tid + i * 256;
                    int kk = idx >> 5, lq = idx & 31;
                    cp16(Bn + kk * 132 + lq * 4, g_WstkT + (size_t)(kb + kk) * 128 + lq * 4);
                }
                cp_commit();
                cp_wait<1>();
            } else {
                cp_wait<0>();
            }
            __syncthreads();
            const float* Arow = Aa + aty * APAD + c * 16;
#pragma unroll
            for (int kk = 0; kk < 16; kk++) {
                float a = Arow[kk];
                float2 bv = *(float2*)(Bc + kk * 132 + atx * 2);
                acc0 = fmaf(a, bv.x, acc0);
                acc1 = fmaf(a, bv.y, acc1);
            }
            __syncthreads();
        }
        {
            int cc = atx * 2;
            float* pv = pvbuf + (s & 1) * 512 + aty * 128 + cc;
            pv[0] = tanhf(acc0 + __ldg(&b_stk[cc]));
            pv[1] = tanhf(acc1 + __ldg(&b_stk[cc + 1]));
        }
        // ---- ACT logits: 24 dots, 3 per warp, shfl-reduced ----
#pragma unroll
        for (int q = 0; q < 3; q++) {
            int d = wwid * 3 + q;
            int bl = d / 6, o = d % 6;
            const float* ar = Aa + bl * APAD;
            const float* wr = W_act + o * H_;
            float sum = 0.f;
#pragma unroll
            for (int k = lane; k < H_; k += 32)
                sum = fmaf(ar[k], __ldg(&wr[k]), sum);
#pragma unroll
            for (int off = 16; off > 0; off >>= 1)
                sum += __shfl_xor_sync(0xffffffffu, sum, off);
            if (lane == 0) lg[d] = sum + __ldg(&b_act[o]);
        }
        __syncthreads();
        if (tid < 8) {
            float l0 = lg[tid * 3 + 0], l1 = lg[tid * 3 + 1], l2 = lg[tid * 3 + 2];
            float mx = fmaxf(l0, fmaxf(l1, l2));
            float e0 = expf(l0 - mx), e1 = expf(l1 - mx), e2 = expf(l2 - mx);
            float inv = 1.f / (e0 + e1 + e2);
            float* P = pbuf + (s & 1) * 24 + tid * 3;
            P[0] = e0 * inv; P[1] = e1 * inv; P[2] = e2 * inv;
        }

        // ---- arrive ----
        __threadfence();
        __syncthreads();
        if (tid == 0) atomicAdd(&g_bar, 1u);

        // ---- stack update for step s-1 (block-local, hidden in wait window) ----
        if (s > 0) {
            int ph = (s - 1) & 1;
#pragma unroll
            for (int half = 0; half < 2; half++) {
                int col = tid + half * 256;
                int stl = col >> 6, ee = col & 63;
                float pp = pbuf[ph * 24 + stl * 3 + 0];
                float po = pbuf[ph * 24 + stl * 3 + 1];
                float pn = pbuf[ph * 24 + stl * 3 + 2];
                float pvv = pvbuf[ph * 512 + (stl >> 1) * 128 + (stl & 1) * 64 + ee];
                float* Sm = stk + stl * 4096;
                float prev = 0.f, cur = Sm[ee];
                float first = pp * pvv;
#pragma unroll 16
                for (int row = 0; row < SSIZE; row++) {
                    float nxt = (row < SSIZE - 1) ? Sm[(row + 1) * 64 + ee] : 0.f;
                    float v;
                    if (row == 0)              v = first;
                    else if (row == SSIZE - 1) v = emp;
                    else v = fmaf(pp, prev, fmaf(po, nxt, pn * cur));
                    Sm[row * 64 + ee] = v;
                    prev = cur; cur = nxt;
                }
            }
        }

        // ---- spin ----
        if (tid == 0) {
            unsigned int target = (unsigned int)NBLK * (unsigned int)(s + 1);
            while (*((volatile unsigned int*)&g_bar) < target) { }
        }
        __syncthreads();
    }

    // ---- final stack update (step S-1) -> global ----
    {
        int ph = (S_ - 1) & 1;
#pragma unroll
        for (int half = 0; half < 2; half++) {
            int col = tid + half * 256;
            int stl = col >> 6, ee = col & 63;
            float pp = pbuf[ph * 24 + stl * 3 + 0];
            float po = pbuf[ph * 24 + stl * 3 + 1];
            float pn = pbuf[ph * 24 + stl * 3 + 2];
            float pvv = pvbuf[ph * 512 + (stl >> 1) * 128 + (stl & 1) * 64 + ee];
            float* Sm = stk + stl * 4096;
            float* dst = stacks_out + (size_t)(blk * 8 + stl) * 4096;
            float prev = 0.f, cur = Sm[ee];
            float first = pp * pvv;
#pragma unroll 16
            for (int row = 0; row < SSIZE; row++) {
                float nxt = (row < SSIZE - 1) ? Sm[(row + 1) * 64 + ee] : 0.f;
                float v;
                if (row == 0)              v = first;
                else if (row == SSIZE - 1) v = emp;
                else v = fmaf(pp, prev, fmaf(po, nxt, pn * cur));
                dst[row * 64 + ee] = v;
                prev = cur; cur = nxt;
            }
        }
    }
}

// ---------------- softmax over S + weighted sum -> final_hidden ----------------
__global__ void __launch_bounds__(256) attn_final_k(const float* __restrict__ outputs,
                                                    const int* __restrict__ tokens,
                                                    const float* __restrict__ ba2,
                                                    float* __restrict__ fh) {
    int b = blockIdx.x;
    int tid = threadIdx.x;
    int lane = tid & 31, wid = tid >> 5;
    __shared__ float a_sm[S_];
    __shared__ float rmax[8];
    __shared__ float rsum[8];

    float v = g_spart[0][tid * B_ + b] + g_spart[1][tid * B_ + b] + ba2[0];
    if (tokens[tid * B_ + b] == 0) v = -1e30f;

    float m = v;
#pragma unroll
    for (int off = 16; off > 0; off >>= 1) m = fmaxf(m, __shfl_xor_sync(0xffffffffu, m, off));
    if (lane == 0) rmax[wid] = m;
    __syncthreads();
    float mx = rmax[0];
#pragma unroll
    for (int i = 1; i < 8; i++) mx = fmaxf(mx, rmax[i]);
    float e = expf(v - mx);
    float sum = e;
#pragma unroll
    for (int off = 16; off > 0; off >>= 1) sum += __shfl_xor_sync(0xffffffffu, sum, off);
    if (lane == 0) rsum[wid] = sum;
    __syncthreads();
    float tot = rsum[0];
#pragma unroll
    for (int i = 1; i < 8; i++) tot += rsum[i];
    a_sm[tid] = e / tot;
    __syncthreads();

    float acc = 0.f;
    for (int s2 = 0; s2 < S_; s2++)
        acc += a_sm[s2] * outputs[((size_t)s2 * B_ + b) * H_ + tid];
    fh[b * H_ + tid] = acc;
}

// ---------------- launch ----------------
extern "C" void kernel_launch(void* const* d_in, const int* in_sizes, int n_in,
                              void* d_out, int out_size) {
    const int*   tokens     = (const int*)d_in[0];
    const float* emb        = (const float*)d_in[1];
    const float* W_ih       = (const float*)d_in[2];
    const float* W_hh       = (const float*)d_in[3];
    const float* b_ih       = (const float*)d_in[4];
    const float* b_hh       = (const float*)d_in[5];
    const float* W_act      = (const float*)d_in[6];
    const float* b_act      = (const float*)d_in[7];
    const float* W_stk      = (const float*)d_in[8];
    const float* b_stk      = (const float*)d_in[9];
    const float* empty_elem = (const float*)d_in[10];
    // d_in[11]=W_up, d_in[12]=W_down : shift matrices, hardcoded
    const float* Wa1        = (const float*)d_in[13];
    const float* ba1        = (const float*)d_in[14];
    const float* Wa2        = (const float*)d_in[15];
    const float* ba2        = (const float*)d_in[16];

    float* out     = (float*)d_out;
    float* outputs = out;
    float* fh      = out + (size_t)S_ * B_ * H_;
    float* stacks  = fh + (size_t)B_ * H_;

    float *pWihT, *pWa1T, *pEMB;
    cudaGetSymbolAddress((void**)&pWihT, g_WihT);
    cudaGetSymbolAddress((void**)&pWa1T, g_Wa1T);
    cudaGetSymbolAddress((void**)&pEMB,  g_EMB_GI);

    static int smem_set = 0;
    if (!smem_set) {
        cudaFuncSetAttribute(persist_k, cudaFuncAttributeMaxDynamicSharedMemorySize, SMEM_DYN);
        smem_set = 1;
    }

    // idx 0-1: prep
    prep1<<<(H3 * H_ + 255) / 256, 256>>>(W_ih, W_hh);
    prep2<<<(B_ * H_ + 255) / 256, 256>>>(W_stk, Wa1);

    // idx 2: EMB_GI = emb @ W_ih^T + b_ih
    {
        dim3 grid(H3 / 128, VOCAB_ / 128);
        sgemm128_k<false><<<grid, 256>>>(emb, pWihT, b_ih, pEMB, nullptr, VOCAB_, H3, H_);
    }

    // idx 3: the whole recurrence (ncu capture slot 5)
    persist_k<<<NBLK, 256, SMEM_DYN>>>(tokens, b_ih, b_hh, W_act, b_act, b_stk,
                                       empty_elem, outputs, stacks);

    // idx 4: attention partials
    {
        dim3 grid(H_ / 128, (S_ * B_) / 128);
        sgemm128_k<true><<<grid, 256>>>(outputs, pWa1T, ba1, nullptr, Wa2, S_ * B_, H_, H_);
    }
    // idx 5: softmax + weighted sum
    attn_final_k<<<B_, 256>>>(outputs, tokens, ba2, fh);
}

// round 15
// speedup vs baseline: 1.6083x; 1.0656x over previous
#include <cuda_runtime.h>
#include <math.h>

#define S_ 256
#define B_ 512
#define H_ 256
#define H3 768
#define VOCAB_ 32000
#define SSIZE 64
#define ELEM 64
#define NBLK 128
#define APAD 260   // Aa row stride (floats)
#define BPAD 200   // B row stride (floats), 800B, 16B multiple
#define ATS 20     // A_T row stride (floats), 80B, 16B multiple

// ---------------- device scratch ----------------
__device__ float g_EMB_GI[VOCAB_ * H3];
__device__ float g_WihT[H_ * H3];
__device__ float g_WhhT[H_ * H3];
__device__ float g_WstkT[H_ * 128];
__device__ float g_Wa1T[H_ * H_];
__device__ float g_h[2][B_ * H_];
__device__ float g_spart[2][S_ * B_];
__device__ unsigned int g_bar;

__device__ __forceinline__ float sigmoidf_(float x) { return 1.f / (1.f + expf(-x)); }

// ---------------- cp.async helpers ----------------
__device__ __forceinline__ void cp16(float* dst_smem, const float* src) {
    unsigned d = (unsigned)__cvta_generic_to_shared(dst_smem);
    asm volatile("cp.async.cg.shared.global [%0], [%1], 16;" :: "r"(d), "l"(src));
}
__device__ __forceinline__ void cp_commit() { asm volatile("cp.async.commit_group;"); }
template <int N>
__device__ __forceinline__ void cp_wait() { asm volatile("cp.async.wait_group %0;" :: "n"(N)); }

// ---------------- prep (persist = my launch idx 3 = ncu slot 5) ----------------
__global__ void prep1(const float* __restrict__ W_ih, const float* __restrict__ W_hh) {
    int idx = blockIdx.x * 256 + threadIdx.x;
    if (idx < H3 * H_) {
        int r = idx % H3, c = idx / H3;
        g_WihT[idx] = W_ih[r * H_ + c];
        g_WhhT[idx] = W_hh[r * H_ + c];
    }
}
__global__ void prep2(const float* __restrict__ W_stk, const float* __restrict__ Wa1) {
    int idx = blockIdx.x * 256 + threadIdx.x;
    if (idx < 128 * H_) { int r = idx % 128, c = idx / 128; g_WstkT[idx] = W_stk[r * H_ + c]; }
    if (idx < H_ * H_) { int r = idx % H_, c = idx / H_; g_Wa1T[idx] = Wa1[r * H_ + c]; }
    if (idx < B_ * H_) g_h[0][idx] = 0.f;
    if (idx == 0) g_bar = 0u;
}

// ---------------- 128x128x16 SGEMM (plain FFMA) ----------------
template <bool SCORE>
__global__ void __launch_bounds__(256) sgemm128_k(
    const float* __restrict__ A, const float* __restrict__ Bm,
    const float* __restrict__ bias, float* __restrict__ C,
    const float* __restrict__ Wa2,
    int M, int N, int K)
{
    __shared__ __align__(16) float As[16][128];
    __shared__ __align__(16) float Bs[16][128];
    int tid = threadIdx.x;
    int m0 = blockIdx.y * 128, n0 = blockIdx.x * 128;
    int tx = tid & 15, ty = tid >> 4;
    float acc[2][2][4][4] = {};

    for (int k0 = 0; k0 < K; k0 += 16) {
#pragma unroll
        for (int i = 0; i < 2; i++) {
            int f = tid * 2 + i;
            int arow = f >> 2, aq = (f & 3) * 4;
            float4 v = *(const float4*)&A[(size_t)(m0 + arow) * K + k0 + aq];
            As[aq + 0][arow] = v.x; As[aq + 1][arow] = v.y;
            As[aq + 2][arow] = v.z; As[aq + 3][arow] = v.w;
            int brow = f >> 5, bc = (f & 31) * 4;
            *(float4*)&Bs[brow][bc] = *(const float4*)&Bm[(size_t)(k0 + brow) * N + n0 + bc];
        }
        __syncthreads();
#pragma unroll
        for (int kk = 0; kk < 16; kk++) {
            float a[2][4], b[2][4];
            *(float4*)a[0] = *(float4*)&As[kk][ty * 4];
            *(float4*)a[1] = *(float4*)&As[kk][ty * 4 + 64];
            *(float4*)b[0] = *(float4*)&Bs[kk][tx * 4];
            *(float4*)b[1] = *(float4*)&Bs[kk][tx * 4 + 64];
#pragma unroll
            for (int ic = 0; ic < 2; ic++)
#pragma unroll
                for (int jc = 0; jc < 2; jc++)
#pragma unroll
                    for (int i = 0; i < 4; i++)
#pragma unroll
                        for (int j = 0; j < 4; j++)
                            acc[ic][jc][i][j] = fmaf(a[ic][i], b[jc][j], acc[ic][jc][i][j]);
        }
        __syncthreads();
    }

    if (!SCORE) {
#pragma unroll
        for (int ic = 0; ic < 2; ic++)
#pragma unroll
            for (int i = 0; i < 4; i++) {
                int m = m0 + ic * 64 + ty * 4 + i;
#pragma unroll
                for (int jc = 0; jc < 2; jc++) {
                    int n = n0 + jc * 64 + tx * 4;
                    float4 o;
                    o.x = acc[ic][jc][i][0] + bias[n + 0];
                    o.y = acc[ic][jc][i][1] + bias[n + 1];
                    o.z = acc[ic][jc][i][2] + bias[n + 2];
                    o.w = acc[ic][jc][i][3] + bias[n + 3];
                    *(float4*)&C[(size_t)m * N + n] = o;
                }
            }
    } else {
        float4 bb[2], ww[2];
#pragma unroll
        for (int jc = 0; jc < 2; jc++) {
            int n = n0 + jc * 64 + tx * 4;
            bb[jc] = *(const float4*)&bias[n];
            ww[jc] = *(const float4*)&Wa2[n];
        }
#pragma unroll
        for (int ic = 0; ic < 2; ic++)
#pragma unroll
            for (int i = 0; i < 4; i++) {
                float p = 0.f;
#pragma unroll
                for (int jc = 0; jc < 2; jc++) {
                    p += tanhf(acc[ic][jc][i][0] + bb[jc].x) * ww[jc].x;
                    p += tanhf(acc[ic][jc][i][1] + bb[jc].y) * ww[jc].y;
                    p += tanhf(acc[ic][jc][i][2] + bb[jc].z) * ww[jc].z;
                    p += tanhf(acc[ic][jc][i][3] + bb[jc].w) * ww[jc].w;
                }
#pragma unroll
                for (int off = 8; off > 0; off >>= 1)
                    p += __shfl_xor_sync(0xffffffffu, p, off);
                if (tx == 0) {
                    int m = m0 + ic * 64 + ty * 4 + i;
                    g_spart[blockIdx.x][m] = p;
                }
            }
    }
}

// ---------------- persistent recurrence: 128 uniform blocks, 1/SM ----------------
// GRU: thread = 4 rows x 1 j-col x 3 gates; A_T staged conflict-free
// (thread = k-col, 4x STS.128 along m, banks fully spread); single sync/chunk.
#define OFF_STK  0                     // 32768
#define OFF_AT   32768                 // 256*ATS = 5120
#define OFF_AA   37888                 // [4][APAD] = 1040
#define OFF_B    38928                 // 2 * 16*BPAD = 6400
#define OFF_BA   45328                 // 2 * 2112 = 4224
#define OFF_PV   49552                 // 2 * 512 = 1024
#define OFF_P    50576                 // 48
#define OFF_LG   50624                 // 24
#define SMEM_DYN ((50656) * 4)

__global__ void __launch_bounds__(256, 1) persist_k(
    const int* __restrict__ tokens,
    const float* __restrict__ b_ih,
    const float* __restrict__ b_hh,
    const float* __restrict__ W_act,
    const float* __restrict__ b_act,
    const float* __restrict__ b_stk,
    const float* __restrict__ empty_elem,
    float* __restrict__ outputs,
    float* __restrict__ stacks_out)
{
    extern __shared__ __align__(16) float smem[];
    float* stk   = smem + OFF_STK;
    float* AT    = smem + OFF_AT;     // [k(256)][16 rows + pad4]
    float* Aa    = smem + OFF_AA;
    float* B0    = smem + OFF_B;
    float* BsA   = smem + OFF_BA;
    float* pvbuf = smem + OFF_PV;
    float* pbuf  = smem + OFF_P;
    float* lg    = smem + OFF_LG;

    int tid = threadIdx.x, blk = blockIdx.x;
    float emp = empty_elem[tid & 63];

    for (int i = tid; i < 8 * 4096; i += 256) stk[i] = empty_elem[i & 63];

    // GRU mapping: tile 16 batches x 64 j (x3 gates)
    int b0 = (blk >> 2) * 16, j0 = (blk & 3) * 64;
    int w = tid >> 5, l = tid & 31;
    int gr0 = (w & 3) * 4;                 // first of 4 rows
    int jo  = (w >> 2) * 32 + l;           // j col 0..63
    // AUX mapping
    int ab0 = blk * 4;
    int aty = tid >> 6, atx = tid & 63;
    int wwid = w, lane = l;

    for (int s = 0; s < S_; s++) {
        const float* hin = g_h[s & 1];
        float* hout = g_h[(s + 1) & 1];

        // ---- stage A_T conflict-free: thread = k-column tid, 16 m values ----
        {
            const float* src = hin + b0 * H_ + tid;
            float vals[16];
#pragma unroll
            for (int m = 0; m < 16; m++) vals[m] = __ldcg(src + m * H_);
            float* d = AT + tid * ATS;
            *(float4*)(d + 0)  = make_float4(vals[0],  vals[1],  vals[2],  vals[3]);
            *(float4*)(d + 4)  = make_float4(vals[4],  vals[5],  vals[6],  vals[7]);
            *(float4*)(d + 8)  = make_float4(vals[8],  vals[9],  vals[10], vals[11]);
            *(float4*)(d + 12) = make_float4(vals[12], vals[13], vals[14], vals[15]);
        }
        // ---- stage Aa (4 AUX rows) ----
        {
            int m = tid >> 6, kq = (tid & 63) * 4;
            float4 v = __ldcg((const float4*)(hin + (ab0 + m) * H_ + kq));
            *(float4*)(Aa + m * APAD + kq) = v;
        }

        // ---- GRU epilogue operand prefetch (hidden under GEMM) ----
        int jj = j0 + jo;
        float grv[4], gzv[4], gnv[4], hpv[4];
#pragma unroll
        for (int i = 0; i < 4; i++) {
            int row = b0 + gr0 + i;
            int tok = __ldg(&tokens[s * B_ + row]);
            const float* gi = (tok == 0) ? b_ih : (g_EMB_GI + (size_t)tok * H3);
            grv[i] = __ldg(gi + jj);
            gzv[i] = __ldg(gi + H_ + jj);
            gnv[i] = __ldg(gi + 2 * H_ + jj);
            hpv[i] = __ldcg(hin + row * H_ + jj);
        }

        // ---- GRU B chunk 0 prefetch ----
#pragma unroll
        for (int i = 0; i < 3; i++) {
            int idx = tid + i * 256;
            int kk = idx / 48, r = idx % 48, g = r >> 4, lq = r & 15;
            cp16(B0 + kk * BPAD + g * 64 + lq * 4,
                 g_WhhT + (size_t)kk * H3 + g * H_ + j0 + lq * 4);
        }
        cp_commit();

        float accr[4] = {}, accz[4] = {}, accn[4] = {};

        // ---- main GEMM loop: ONE sync per chunk ----
        for (int c = 0; c < 16; c++) {
            cp_wait<0>();          // chunk c landed (only group in flight)
            __syncthreads();       // c visible to all; all warps done reading buf (c+1)&1
            if (c + 1 < 16) {
                float* Bn = B0 + ((c + 1) & 1) * (16 * BPAD);
                int kb = (c + 1) * 16;
#pragma unroll
                for (int i = 0; i < 3; i++) {
                    int idx = tid + i * 256;
                    int kk = idx / 48, r = idx % 48, g = r >> 4, lq = r & 15;
                    cp16(Bn + kk * BPAD + g * 64 + lq * 4,
                         g_WhhT + (size_t)(kb + kk) * H3 + g * H_ + j0 + lq * 4);
                }
                cp_commit();
            }
            float* Bc = B0 + (c & 1) * (16 * BPAD);
            const float* ATc = AT + (c * 16) * ATS + gr0;
#pragma unroll
            for (int kk = 0; kk < 16; kk++) {
                float4 av = *(const float4*)(ATc + kk * ATS);   // broadcast, 1 phase
                float br = Bc[kk * BPAD + jo];
                float bz = Bc[kk * BPAD + 64 + jo];
                float bn = Bc[kk * BPAD + 128 + jo];
                accr[0] = fmaf(av.x, br, accr[0]); accr[1] = fmaf(av.y, br, accr[1]);
                accr[2] = fmaf(av.z, br, accr[2]); accr[3] = fmaf(av.w, br, accr[3]);
                accz[0] = fmaf(av.x, bz, accz[0]); accz[1] = fmaf(av.y, bz, accz[1]);
                accz[2] = fmaf(av.z, bz, accz[2]); accz[3] = fmaf(av.w, bz, accz[3]);
                accn[0] = fmaf(av.x, bn, accn[0]); accn[1] = fmaf(av.y, bn, accn[1]);
                accn[2] = fmaf(av.z, bn, accn[2]); accn[3] = fmaf(av.w, bn, accn[3]);
            }
        }

        // ---- GRU epilogue (4 rows x 1 col) ----
        {
            float bhr = __ldg(b_hh + jj);
            float bhz = __ldg(b_hh + H_ + jj);
            float bhn = __ldg(b_hh + 2 * H_ + jj);
#pragma unroll
            for (int i = 0; i < 4; i++) {
                int row = b0 + gr0 + i;
                float rr = sigmoidf_(grv[i] + accr[i] + bhr);
                float zz = sigmoidf_(gzv[i] + accz[i] + bhz);
                float nn = tanhf(gnv[i] + rr * (accn[i] + bhn));
                float o = (1.f - zz) * nn + zz * hpv[i];
                hout[row * H_ + jj] = o;
                outputs[((size_t)s * B_ + row) * H_ + jj] = o;
            }
        }

        // ---- AUX GEMM (unchanged): PV = tanh(h[ab0..+3] @ WstkT + b_stk) ----
#pragma unroll
        for (int i = 0; i < 2; i++) {
            int idx = tid + i * 256;
            int kk = idx >> 5, lq = idx & 31;
            cp16(BsA + kk * 132 + lq * 4, g_WstkT + (size_t)kk * 128 + lq * 4);
        }
        cp_commit();
        float acc0 = 0.f, acc1 = 0.f;
        for (int c = 0; c < 16; c++) {
            float* Bc = BsA + (c & 1) * 2112;
            if (c + 1 < 16) {
                float* Bn = BsA + ((c + 1) & 1) * 2112;
                int kb = (c + 1) * 16;
#pragma unroll
                for (int i = 0; i < 2; i++) {
                    int idx = tid + i * 256;
                    int kk = idx >> 5, lq = idx & 31;
                    cp16(Bn + kk * 132 + lq * 4, g_WstkT + (size_t)(kb + kk) * 128 + lq * 4);
                }
                cp_commit();
                cp_wait<1>();
            } else {
                cp_wait<0>();
            }
            __syncthreads();
            const float* Arow = Aa + aty * APAD + c * 16;
#pragma unroll
            for (int kk = 0; kk < 16; kk++) {
                float a = Arow[kk];
                float2 bv = *(float2*)(Bc + kk * 132 + atx * 2);
                acc0 = fmaf(a, bv.x, acc0);
                acc1 = fmaf(a, bv.y, acc1);
            }
            __syncthreads();
        }
        {
            int cc = atx * 2;
            float* pv = pvbuf + (s & 1) * 512 + aty * 128 + cc;
            pv[0] = tanhf(acc0 + __ldg(&b_stk[cc]));
            pv[1] = tanhf(acc1 + __ldg(&b_stk[cc + 1]));
        }
        // ---- ACT logits: 24 dots, 3 per warp, shfl-reduced ----
#pragma unroll
        for (int q = 0; q < 3; q++) {
            int d = wwid * 3 + q;
            int bl = d / 6, o = d % 6;
            const float* ar = Aa + bl * APAD;
            const float* wr = W_act + o * H_;
            float sum = 0.f;
#pragma unroll
            for (int k = lane; k < H_; k += 32)
                sum = fmaf(ar[k], __ldg(&wr[k]), sum);
#pragma unroll
            for (int off = 16; off > 0; off >>= 1)
                sum += __shfl_xor_sync(0xffffffffu, sum, off);
            if (lane == 0) lg[d] = sum + __ldg(&b_act[o]);
        }
        __syncthreads();
        if (tid < 8) {
            float l0 = lg[tid * 3 + 0], l1 = lg[tid * 3 + 1], l2 = lg[tid * 3 + 2];
            float mx = fmaxf(l0, fmaxf(l1, l2));
            float e0 = expf(l0 - mx), e1 = expf(l1 - mx), e2 = expf(l2 - mx);
            float inv = 1.f / (e0 + e1 + e2);
            float* P = pbuf + (s & 1) * 24 + tid * 3;
            P[0] = e0 * inv; P[1] = e1 * inv; P[2] = e2 * inv;
        }

        // ---- arrive ----
        __threadfence();
        __syncthreads();
        if (tid == 0) atomicAdd(&g_bar, 1u);

        // ---- stack update for step s-1 (block-local, hidden in wait window) ----
        if (s > 0) {
            int ph = (s - 1) & 1;
#pragma unroll
            for (int half = 0; half < 2; half++) {
                int col = tid + half * 256;
                int stl = col >> 6, ee = col & 63;
                float pp = pbuf[ph * 24 + stl * 3 + 0];
                float po = pbuf[ph * 24 + stl * 3 + 1];
                float pn = pbuf[ph * 24 + stl * 3 + 2];
                float pvv = pvbuf[ph * 512 + (stl >> 1) * 128 + (stl & 1) * 64 + ee];
                float* Sm = stk + stl * 4096;
                float prev = 0.f, cur = Sm[ee];
                float first = pp * pvv;
#pragma unroll 16
                for (int row = 0; row < SSIZE; row++) {
                    float nxt = (row < SSIZE - 1) ? Sm[(row + 1) * 64 + ee] : 0.f;
                    float v;
                    if (row == 0)              v = first;
                    else if (row == SSIZE - 1) v = emp;
                    else v = fmaf(pp, prev, fmaf(po, nxt, pn * cur));
                    Sm[row * 64 + ee] = v;
                    prev = cur; cur = nxt;
                }
            }
        }

        // ---- spin ----
        if (tid == 0) {
            unsigned int target = (unsigned int)NBLK * (unsigned int)(s + 1);
            while (*((volatile unsigned int*)&g_bar) < target) { }
        }
        __syncthreads();
    }

    // ---- final stack update (step S-1) -> global ----
    {
        int ph = (S_ - 1) & 1;
#pragma unroll
        for (int half = 0; half < 2; half++) {
            int col = tid + half * 256;
            int stl = col >> 6, ee = col & 63;
            float pp = pbuf[ph * 24 + stl * 3 + 0];
            float po = pbuf[ph * 24 + stl * 3 + 1];
            float pn = pbuf[ph * 24 + stl * 3 + 2];
            float pvv = pvbuf[ph * 512 + (stl >> 1) * 128 + (stl & 1) * 64 + ee];
            float* Sm = stk + stl * 4096;
            float* dst = stacks_out + (size_t)(blk * 8 + stl) * 4096;
            float prev = 0.f, cur = Sm[ee];
            float first = pp * pvv;
#pragma unroll 16
            for (int row = 0; row < SSIZE; row++) {
                float nxt = (row < SSIZE - 1) ? Sm[(row + 1) * 64 + ee] : 0.f;
                float v;
                if (row == 0)              v = first;
                else if (row == SSIZE - 1) v = emp;
                else v = fmaf(pp, prev, fmaf(po, nxt, pn * cur));
                dst[row * 64 + ee] = v;
                prev = cur; cur = nxt;
            }
        }
    }
}

// ---------------- softmax over S + weighted sum -> final_hidden ----------------
__global__ void __launch_bounds__(256) attn_final_k(const float* __restrict__ outputs,
                                                    const int* __restrict__ tokens,
                                                    const float* __restrict__ ba2,
                                                    float* __restrict__ fh) {
    int b = blockIdx.x;
    int tid = threadIdx.x;
    int lane = tid & 31, wid = tid >> 5;
    __shared__ float a_sm[S_];
    __shared__ float rmax[8];
    __shared__ float rsum[8];

    float v = g_spart[0][tid * B_ + b] + g_spart[1][tid * B_ + b] + ba2[0];
    if (tokens[tid * B_ + b] == 0) v = -1e30f;

    float m = v;
#pragma unroll
    for (int off = 16; off > 0; off >>= 1) m = fmaxf(m, __shfl_xor_sync(0xffffffffu, m, off));
    if (lane == 0) rmax[wid] = m;
    __syncthreads();
    float mx = rmax[0];
#pragma unroll
    for (int i = 1; i < 8; i++) mx = fmaxf(mx, rmax[i]);
    float e = expf(v - mx);
    float sum = e;
#pragma unroll
    for (int off = 16; off > 0; off >>= 1) sum += __shfl_xor_sync(0xffffffffu, sum, off);
    if (lane == 0) rsum[wid] = sum;
    __syncthreads();
    float tot = rsum[0];
#pragma unroll
    for (int i = 1; i < 8; i++) tot += rsum[i];
    a_sm[tid] = e / tot;
    __syncthreads();

    float acc = 0.f;
    for (int s2 = 0; s2 < S_; s2++)
        acc += a_sm[s2] * outputs[((size_t)s2 * B_ + b) * H_ + tid];
    fh[b * H_ + tid] = acc;
}

// ---------------- launch ----------------
extern "C" void kernel_launch(void* const* d_in, const int* in_sizes, int n_in,
                              void* d_out, int out_size) {
    const int*   tokens     = (const int*)d_in[0];
    const float* emb        = (const float*)d_in[1];
    const float* W_ih       = (const float*)d_in[2];
    const float* W_hh       = (const float*)d_in[3];
    const float* b_ih       = (const float*)d_in[4];
    const float* b_hh       = (const float*)d_in[5];
    const float* W_act      = (const float*)d_in[6];
    const float* b_act      = (const float*)d_in[7];
    const float* W_stk      = (const float*)d_in[8];
    const float* b_stk      = (const float*)d_in[9];
    const float* empty_elem = (const float*)d_in[10];
    // d_in[11]=W_up, d_in[12]=W_down : shift matrices, hardcoded
    const float* Wa1        = (const float*)d_in[13];
    const float* ba1        = (const float*)d_in[14];
    const float* Wa2        = (const float*)d_in[15];
    const float* ba2        = (const float*)d_in[16];

    float* out     = (float*)d_out;
    float* outputs = out;
    float* fh      = out + (size_t)S_ * B_ * H_;
    float* stacks  = fh + (size_t)B_ * H_;

    float *pWihT, *pWa1T, *pEMB;
    cudaGetSymbolAddress((void**)&pWihT, g_WihT);
    cudaGetSymbolAddress((void**)&pWa1T, g_Wa1T);
    cudaGetSymbolAddress((void**)&pEMB,  g_EMB_GI);

    static int smem_set = 0;
    if (!smem_set) {
        cudaFuncSetAttribute(persist_k, cudaFuncAttributeMaxDynamicSharedMemorySize, SMEM_DYN);
        smem_set = 1;
    }

    // idx 0-1: prep
    prep1<<<(H3 * H_ + 255) / 256, 256>>>(W_ih, W_hh);
    prep2<<<(B_ * H_ + 255) / 256, 256>>>(W_stk, Wa1);

    // idx 2: EMB_GI = emb @ W_ih^T + b_ih
    {
        dim3 grid(H3 / 128, VOCAB_ / 128);
        sgemm128_k<false><<<grid, 256>>>(emb, pWihT, b_ih, pEMB, nullptr, VOCAB_, H3, H_);
    }

    // idx 3: the whole recurrence (ncu capture slot 5)
    persist_k<<<NBLK, 256, SMEM_DYN>>>(tokens, b_ih, b_hh, W_act, b_act, b_stk,
                                       empty_elem, outputs, stacks);

    // idx 4: attention partials
    {
        dim3 grid(H_ / 128, (S_ * B_) / 128);
        sgemm128_k<true><<<grid, 256>>>(outputs, pWa1T, ba1, nullptr, Wa2, S_ * B_, H_, H_);
    }
    // idx 5: softmax + weighted sum
    attn_final_k<<<B_, 256>>>(outputs, tokens, ba2, fh);
}